// round 8
// baseline (speedup 1.0000x reference)
#include <cuda_runtime.h>
#include <cstdint>

#define NBOX   8192
#define CLS    81
#define NPAD   300
#define NWORDS (NBOX / 32)      // 256 words per mask row
#define NCH    (NBOX / 64)      // 128 scan chunks of 64 boxes

// ------------------------- device scratch (static, no allocs) --------------
__device__ float4             g_selv[NBOX];     // decoded boxes (orig order)
__device__ unsigned long long g_key[NBOX];      // composite sort keys
__device__ float4             g_sbox[NBOX];     // boxes in sorted order
__device__ float              g_sarea[NBOX];    // areas in sorted order
__device__ int                g_orig[NBOX];     // sorted pos -> original idx
__device__ unsigned           g_masks[(size_t)NBOX * NWORDS]; // sorted-space IoU>0.5

// ---------------------------------------------------------------------------
// Kernel 1: per-row argmax / max + bbox decode + sort-key build. 1 warp/row.
// ---------------------------------------------------------------------------
__global__ void decode_kernel(const float* __restrict__ meta,
                              const float* __restrict__ deltas,
                              const float* __restrict__ proposals,
                              const float* __restrict__ scores) {
    int row  = (int)((blockIdx.x * blockDim.x + threadIdx.x) >> 5);
    int lane = threadIdx.x & 31;
    if (row >= NBOX) return;

    const float* srow = scores + (size_t)row * CLS;
    float best = -1.0f;
    int   bidx = 0x7FFFFFFF;
    float ms   = -1.0f;
    for (int j = lane; j < CLS; j += 32) {
        float v = srow[j];
        if (v > best) { best = v; bidx = j; }
        if (j >= 1) ms = fmaxf(ms, v);
    }
    #pragma unroll
    for (int off = 16; off; off >>= 1) {
        float ov = __shfl_down_sync(0xffffffffu, best, off);
        int   oi = __shfl_down_sync(0xffffffffu, bidx, off);
        float om = __shfl_down_sync(0xffffffffu, ms,   off);
        if (ov > best || (ov == best && oi < bidx)) { best = ov; bidx = oi; }
        ms = fmaxf(ms, om);
    }

    if (lane == 0) {
        float scale = meta[2];
        const float* p = proposals + (size_t)row * 4;
        float x1 = p[0] / scale, y1 = p[1] / scale;
        float x2 = p[2] / scale, y2 = p[3] / scale;
        float w  = x2 - x1 + 1.0f, h = y2 - y1 + 1.0f;
        float cx = x1 + 0.5f * w,  cy = y1 + 0.5f * h;

        const float* d = deltas + (size_t)row * (4 * CLS) + 4 * bidx;
        float pcx = d[0] * w + cx;
        float pcy = d[1] * h + cy;
        float pw  = expf(d[2]) * w;
        float ph  = expf(d[3]) * h;

        float W1 = meta[1] - 1.0f;
        float H1 = meta[0] - 1.0f;
        float ox1 = fminf(fmaxf(pcx - 0.5f * pw, 0.0f), W1);
        float oy1 = fminf(fmaxf(pcy - 0.5f * ph, 0.0f), H1);
        float ox2 = fminf(fmaxf(pcx + 0.5f * pw, 0.0f), W1);
        float oy2 = fminf(fmaxf(pcy + 0.5f * ph, 0.0f), H1);

        g_selv[row] = make_float4(ox1, oy1, ox2, oy2);
        unsigned int sb = __float_as_uint(ms);   // scores >= 0 -> monotonic bits
        g_key[row] = ((unsigned long long)sb << 13) |
                     (unsigned long long)(8191 - row);   // all keys distinct
    }
}

// ---------------------------------------------------------------------------
// Kernel 2: rank-by-counting + scatter into sorted order. 256 blocks.
// ---------------------------------------------------------------------------
__global__ void __launch_bounds__(256)
rank_kernel() {
    extern __shared__ unsigned long long keys[];   // 64 KB
    const int tid = threadIdx.x;
    for (int i = tid; i < NBOX; i += 256) keys[i] = g_key[i];
    __syncthreads();

    const int warp = tid >> 5, lane = tid & 31;
    const int row0 = blockIdx.x * 32 + warp * 4;

    unsigned long long rk0 = keys[row0 + 0];
    unsigned long long rk1 = keys[row0 + 1];
    unsigned long long rk2 = keys[row0 + 2];
    unsigned long long rk3 = keys[row0 + 3];
    int c0 = 0, c1 = 0, c2 = 0, c3 = 0;

    #pragma unroll 4
    for (int c = lane; c < NBOX; c += 32) {
        unsigned long long kc = keys[c];
        c0 += (kc > rk0);
        c1 += (kc > rk1);
        c2 += (kc > rk2);
        c3 += (kc > rk3);
    }
    #pragma unroll
    for (int off = 16; off; off >>= 1) {
        c0 += __shfl_down_sync(0xffffffffu, c0, off);
        c1 += __shfl_down_sync(0xffffffffu, c1, off);
        c2 += __shfl_down_sync(0xffffffffu, c2, off);
        c3 += __shfl_down_sync(0xffffffffu, c3, off);
    }
    if (lane == 0) {
        int rr[4] = {c0, c1, c2, c3};
        #pragma unroll
        for (int q = 0; q < 4; q++) {
            int i = row0 + q, r = rr[q];
            float4 b = g_selv[i];
            g_sbox[r]  = b;
            g_sarea[r] = fmaxf(b.z - b.x, 0.0f) * fmaxf(b.w - b.y, 0.0f);
            g_orig[r]  = i;
        }
    }
}

// ---------------------------------------------------------------------------
// Kernel 3: sorted-space IoU>0.5 bitmask, upper triangle only.
// ---------------------------------------------------------------------------
__global__ void __launch_bounds__(256)
mask_kernel() {
    __shared__ float4 rbs[32];
    __shared__ float  ras[32];
    __shared__ float4 cbT[32 * 33];
    __shared__ float  caT[32 * 33];

    const int m  = blockIdx.x;
    const int rb = m & 255;
    const int cb = m >> 8;
    if (cb < (rb >> 5)) return;

    const int rowbase = rb * 32;
    const int colbase = cb * 1024;
    const int tid = threadIdx.x;

    if (tid < 32) {
        rbs[tid] = g_sbox[rowbase + tid];
        ras[tid] = g_sarea[rowbase + tid];
    }
    for (int jj = tid; jj < 1024; jj += 256) {
        int w = jj >> 5, bb = jj & 31;
        cbT[bb * 33 + w] = g_sbox[colbase + jj];
        caT[bb * 33 + w] = g_sarea[colbase + jj];
    }
    __syncthreads();

    const int r0 = tid >> 5;
    const int w  = tid & 31;
    float4 bi[4];
    float  si[4];
    #pragma unroll
    for (int k = 0; k < 4; k++) {
        bi[k] = rbs[r0 + 8 * k];
        si[k] = ras[r0 + 8 * k] + 1e-8f;
    }
    unsigned bits0 = 0, bits1 = 0, bits2 = 0, bits3 = 0;

    #pragma unroll
    for (int b = 0; b < 32; b++) {
        float4 bj = cbT[b * 33 + w];
        float  aj = caT[b * 33 + w];
        #pragma unroll
        for (int k = 0; k < 4; k++) {
            float xx1 = fmaxf(bi[k].x, bj.x), yy1 = fmaxf(bi[k].y, bj.y);
            float xx2 = fminf(bi[k].z, bj.z), yy2 = fminf(bi[k].w, bj.w);
            float iw  = fmaxf(xx2 - xx1, 0.0f);
            float ih  = fmaxf(yy2 - yy1, 0.0f);
            float inter = iw * ih;
            unsigned p = (3.0f * inter > si[k] + aj) ? (1u << b) : 0u;
            if (k == 0) bits0 |= p;
            else if (k == 1) bits1 |= p;
            else if (k == 2) bits2 |= p;
            else bits3 |= p;
        }
    }
    size_t base = (size_t)rowbase * NWORDS + (size_t)cb * 32 + w;
    g_masks[base + (size_t)(r0 +  0) * NWORDS] = bits0;
    g_masks[base + (size_t)(r0 +  8) * NWORDS] = bits1;
    g_masks[base + (size_t)(r0 + 16) * NWORDS] = bits2;
    g_masks[base + (size_t)(r0 + 24) * NWORDS] = bits3;
}

// ---------------------------------------------------------------------------
// Kernel 4: greedy scan with ALL static operands preloaded to smem (192 KB).
//  prologue        : conf/n1/n2 for all 128 chunks -> dynamic smem
//  thread 0        : resolution purely on smem (no gmem on chain)
//  tids 32..255    : row-OR suppression for keeps(c-1), issued iter c,
//                    applied iter c+2 (register pipeline, no STS stall)
//  supfix = n1acc(keeps c-1) | n2acc(keeps c-2) covers the lag gap.
// ---------------------------------------------------------------------------
#define SCAN_SMEM (3 * NBOX * 8)    // 196608 B: conf + n1 + n2

__global__ void __launch_bounds__(256)
scan_kernel(const float* __restrict__ scores, float* __restrict__ out) {
    extern __shared__ unsigned long long ops[];
    unsigned long long* conf = ops;                // [NBOX] diag words
    unsigned long long* n1   = ops + NBOX;         // [NBOX] chunk+1 words
    unsigned long long* n2   = ops + 2 * NBOX;     // [NBOX] chunk+2 words

    __shared__ unsigned           sup_s[NWORDS];
    __shared__ unsigned long long kbuf64[2];
    __shared__ int                kcnt[2];
    __shared__ int                s_keep[NPAD];

    const int tid = threadIdx.x;
    sup_s[tid] = 0u;
    if (tid == 0) { kbuf64[0] = kbuf64[1] = 0ull; kcnt[0] = kcnt[1] = 0; }

    // ---- prologue: preload all chunk operands (static addresses) ----------
    // row i = c*64 + r ; u64 row stride = NWORDS/2 = 128 ; diag u64 idx = c
    const unsigned long long* m64 = (const unsigned long long*)g_masks;
    for (int i = tid; i < NBOX; i += 256) {
        const int c = i >> 6;
        const unsigned long long* r = m64 + (size_t)i * (NWORDS / 2);
        int i1 = c + 1; if (i1 > NWORDS / 2 - 1) i1 = NWORDS / 2 - 1;
        int i2 = c + 2; if (i2 > NWORDS / 2 - 1) i2 = NWORDS / 2 - 1;
        conf[i] = __ldg(r + c);
        n1[i]   = __ldg(r + i1);
        n2[i]   = __ldg(r + i2);
    }
    __syncthreads();

    unsigned long long supfix = 0ull, carry = 0ull;   // thread 0 only
    unsigned b1a = 0u, b1b = 0u, b2a = 0u, b2b = 0u;  // bacc register pipeline
    const int w0 = tid - 32;
    const int w1 = (w0 >= 0 && w0 < 32) ? w0 + 224 : -1;
    int nk_local = 0;                                  // thread 0 only

    for (int c = 0; c < NCH; c++) {
        // ---- stage A: apply suppression loaded 2 iters ago (keeps c-3) ----
        if (tid >= 32) {
            if (b2a) sup_s[w0] |= b2a;
            if (w1 >= 0 && b2b) sup_s[w1] |= b2b;
        }
        __syncthreads();   // sup_s(<=c-2 effective), kbuf/kcnt(c-1) visible
        if (c > 0 && kcnt[(c - 1) & 1] >= NPAD) break;   // uniform

        if (tid == 0) {
            // ---- resolution: pure smem/register chain ----
            const int b    = c & 1;
            const int base = c * 64;
            unsigned long long sup64 =
                *(const unsigned long long*)&sup_s[2 * c];
            unsigned long long am = ~(sup64 | supfix);
            unsigned long long keepm = 0ull, n1acc = 0ull, n2acc = 0ull;
            int k2 = nk_local;
            while (am) {
                int l = __ffsll((long long)am) - 1;
                keepm |= 1ull << l;
                unsigned long long cl = conf[base + l];
                n1acc |= n1[base + l];
                n2acc |= n2[base + l];
                am &= ~cl;
                am &= ~(1ull << l);
                if (k2 < NPAD) s_keep[k2++] = base + l;
            }
            kbuf64[b] = keepm;
            kcnt[b]   = k2;
            nk_local  = k2;
            supfix = carry | n1acc;   // covers keeps(c) @ chunk c+1
            carry  = n2acc;           // covers keeps(c) @ chunk c+2
        } else {
            // ---- stage B: issue row-OR loads for keeps(c-1); applied c+2 --
            unsigned a0 = 0u, a1 = 0u;
            if (c > 0) {
                unsigned long long km = kbuf64[(c - 1) & 1];
                const size_t pb = (size_t)(c - 1) * 64;
                while (km) {
                    int l = __ffsll((long long)km) - 1; km &= km - 1;
                    const unsigned* row = &g_masks[(pb + l) * NWORDS];
                    a0 |= __ldg(row + w0);
                    if (w1 >= 0) a1 |= __ldg(row + w1);
                }
            }
            b2a = b1a; b2b = b1b;     // shift: previous issue -> apply next
            b1a = a0;  b1b = a1;
        }
    }
    __syncthreads();
    const int nk = (kcnt[0] > kcnt[1]) ? kcnt[0] : kcnt[1];   // cumulative

    // ---- outputs: boxes (300*4) then scores (300*81); zero invalid rows ----
    for (int idx = tid; idx < NPAD * 4; idx += 256) {
        int r = idx >> 2, cc = idx & 3;
        float v = 0.0f;
        if (r < nk) {
            float4 b = g_sbox[s_keep[r]];
            v = (cc == 0) ? b.x : (cc == 1) ? b.y : (cc == 2) ? b.z : b.w;
        }
        out[idx] = v;
    }
    for (int idx = tid; idx < NPAD * CLS; idx += 256) {
        int r = idx / CLS, cc = idx - r * CLS;
        float v = 0.0f;
        if (r < nk)
            v = scores[(size_t)g_orig[s_keep[r]] * CLS + cc];
        out[NPAD * 4 + idx] = v;
    }
}

// ---------------------------------------------------------------------------
extern "C" void kernel_launch(void* const* d_in, const int* in_sizes, int n_in,
                              void* d_out, int out_size) {
    const float* meta      = (const float*)d_in[0];
    const float* deltas    = (const float*)d_in[1];
    const float* proposals = (const float*)d_in[2];
    const float* scores    = (const float*)d_in[3];
    float* out = (float*)d_out;

    decode_kernel<<<NBOX / 8, 256>>>(meta, deltas, proposals, scores);

    cudaFuncSetAttribute(rank_kernel,
                         cudaFuncAttributeMaxDynamicSharedMemorySize, 65536);
    rank_kernel<<<256, 256, 65536>>>();

    mask_kernel<<<2048, 256>>>();

    cudaFuncSetAttribute(scan_kernel,
                         cudaFuncAttributeMaxDynamicSharedMemorySize, SCAN_SMEM);
    scan_kernel<<<1, 256, SCAN_SMEM>>>(scores, out);
}

// round 9
// speedup vs baseline: 1.0014x; 1.0014x over previous
#include <cuda_runtime.h>
#include <cstdint>

#define NBOX   8192
#define CLS    81
#define NPAD   300
#define NWORDS (NBOX / 32)      // 256 words per mask row
#define NCH2   (NBOX / 128)     // 64 scan chunks of 128 boxes

// ------------------------- device scratch (static, no allocs) --------------
__device__ float4             g_selv[NBOX];     // decoded boxes (orig order)
__device__ unsigned long long g_key[NBOX];      // composite sort keys
__device__ float4             g_sbox[NBOX];     // boxes in sorted order
__device__ float              g_sarea[NBOX];    // areas in sorted order
__device__ int                g_orig[NBOX];     // sorted pos -> original idx
__device__ unsigned           g_masks[(size_t)NBOX * NWORDS]; // sorted-space IoU>0.5

// ---------------------------------------------------------------------------
// Kernel 1: per-row argmax / max + bbox decode + sort-key build. 1 warp/row.
// ---------------------------------------------------------------------------
__global__ void decode_kernel(const float* __restrict__ meta,
                              const float* __restrict__ deltas,
                              const float* __restrict__ proposals,
                              const float* __restrict__ scores) {
    int row  = (int)((blockIdx.x * blockDim.x + threadIdx.x) >> 5);
    int lane = threadIdx.x & 31;
    if (row >= NBOX) return;

    const float* srow = scores + (size_t)row * CLS;
    float best = -1.0f;
    int   bidx = 0x7FFFFFFF;
    float ms   = -1.0f;
    for (int j = lane; j < CLS; j += 32) {
        float v = srow[j];
        if (v > best) { best = v; bidx = j; }
        if (j >= 1) ms = fmaxf(ms, v);
    }
    #pragma unroll
    for (int off = 16; off; off >>= 1) {
        float ov = __shfl_down_sync(0xffffffffu, best, off);
        int   oi = __shfl_down_sync(0xffffffffu, bidx, off);
        float om = __shfl_down_sync(0xffffffffu, ms,   off);
        if (ov > best || (ov == best && oi < bidx)) { best = ov; bidx = oi; }
        ms = fmaxf(ms, om);
    }

    if (lane == 0) {
        float scale = meta[2];
        const float* p = proposals + (size_t)row * 4;
        float x1 = p[0] / scale, y1 = p[1] / scale;
        float x2 = p[2] / scale, y2 = p[3] / scale;
        float w  = x2 - x1 + 1.0f, h = y2 - y1 + 1.0f;
        float cx = x1 + 0.5f * w,  cy = y1 + 0.5f * h;

        const float* d = deltas + (size_t)row * (4 * CLS) + 4 * bidx;
        float pcx = d[0] * w + cx;
        float pcy = d[1] * h + cy;
        float pw  = expf(d[2]) * w;
        float ph  = expf(d[3]) * h;

        float W1 = meta[1] - 1.0f;
        float H1 = meta[0] - 1.0f;
        float ox1 = fminf(fmaxf(pcx - 0.5f * pw, 0.0f), W1);
        float oy1 = fminf(fmaxf(pcy - 0.5f * ph, 0.0f), H1);
        float ox2 = fminf(fmaxf(pcx + 0.5f * pw, 0.0f), W1);
        float oy2 = fminf(fmaxf(pcy + 0.5f * ph, 0.0f), H1);

        g_selv[row] = make_float4(ox1, oy1, ox2, oy2);
        unsigned int sb = __float_as_uint(ms);   // scores >= 0 -> monotonic bits
        g_key[row] = ((unsigned long long)sb << 13) |
                     (unsigned long long)(8191 - row);   // all keys distinct
    }
}

// ---------------------------------------------------------------------------
// Kernel 2: rank-by-counting + scatter into sorted order. 256 blocks.
// ---------------------------------------------------------------------------
__global__ void __launch_bounds__(256)
rank_kernel() {
    extern __shared__ unsigned long long keys[];   // 64 KB
    const int tid = threadIdx.x;
    for (int i = tid; i < NBOX; i += 256) keys[i] = g_key[i];
    __syncthreads();

    const int warp = tid >> 5, lane = tid & 31;
    const int row0 = blockIdx.x * 32 + warp * 4;

    unsigned long long rk0 = keys[row0 + 0];
    unsigned long long rk1 = keys[row0 + 1];
    unsigned long long rk2 = keys[row0 + 2];
    unsigned long long rk3 = keys[row0 + 3];
    int c0 = 0, c1 = 0, c2 = 0, c3 = 0;

    #pragma unroll 4
    for (int c = lane; c < NBOX; c += 32) {
        unsigned long long kc = keys[c];
        c0 += (kc > rk0);
        c1 += (kc > rk1);
        c2 += (kc > rk2);
        c3 += (kc > rk3);
    }
    #pragma unroll
    for (int off = 16; off; off >>= 1) {
        c0 += __shfl_down_sync(0xffffffffu, c0, off);
        c1 += __shfl_down_sync(0xffffffffu, c1, off);
        c2 += __shfl_down_sync(0xffffffffu, c2, off);
        c3 += __shfl_down_sync(0xffffffffu, c3, off);
    }
    if (lane == 0) {
        int rr[4] = {c0, c1, c2, c3};
        #pragma unroll
        for (int q = 0; q < 4; q++) {
            int i = row0 + q, r = rr[q];
            float4 b = g_selv[i];
            g_sbox[r]  = b;
            g_sarea[r] = fmaxf(b.z - b.x, 0.0f) * fmaxf(b.w - b.y, 0.0f);
            g_orig[r]  = i;
        }
    }
}

// ---------------------------------------------------------------------------
// Kernel 3: sorted-space IoU>0.5 bitmask, upper-triangle tiles only.
// 1152 live blocks (no dead blocks); tile = 32 rows x 1024 cols.
// ---------------------------------------------------------------------------
__constant__ int c_prefix[9] = {0, 256, 480, 672, 832, 960, 1056, 1120, 1152};

__global__ void __launch_bounds__(256)
mask_kernel() {
    __shared__ float4 rbs[32];
    __shared__ float  ras[32];
    __shared__ float4 cbT[32 * 33];
    __shared__ float  caT[32 * 33];

    // triangular tile id -> (rb, cb) with cb >= rb/32
    const int t = blockIdx.x;
    int g = 0;
    #pragma unroll
    for (int h = 1; h < 8; h++) g += (t >= c_prefix[h]);
    const int tp   = t - c_prefix[g];
    const int span = 8 - g;
    const int r    = tp / span;
    const int rb   = g * 32 + r;
    const int cb   = g + (tp - r * span);

    const int rowbase = rb * 32;
    const int colbase = cb * 1024;
    const int tid = threadIdx.x;

    if (tid < 32) {
        rbs[tid] = g_sbox[rowbase + tid];
        ras[tid] = g_sarea[rowbase + tid];
    }
    for (int jj = tid; jj < 1024; jj += 256) {
        int w = jj >> 5, bb = jj & 31;
        cbT[bb * 33 + w] = g_sbox[colbase + jj];
        caT[bb * 33 + w] = g_sarea[colbase + jj];
    }
    __syncthreads();

    const int r0 = tid >> 5;
    const int w  = tid & 31;
    float4 bi[4];
    float  si[4];
    #pragma unroll
    for (int k = 0; k < 4; k++) {
        bi[k] = rbs[r0 + 8 * k];
        si[k] = ras[r0 + 8 * k] + 1e-8f;
    }
    unsigned bits0 = 0, bits1 = 0, bits2 = 0, bits3 = 0;

    #pragma unroll
    for (int b = 0; b < 32; b++) {
        float4 bj = cbT[b * 33 + w];
        float  aj = caT[b * 33 + w];
        #pragma unroll
        for (int k = 0; k < 4; k++) {
            float xx1 = fmaxf(bi[k].x, bj.x), yy1 = fmaxf(bi[k].y, bj.y);
            float xx2 = fminf(bi[k].z, bj.z), yy2 = fminf(bi[k].w, bj.w);
            float iw  = fmaxf(xx2 - xx1, 0.0f);
            float ih  = fmaxf(yy2 - yy1, 0.0f);
            float inter = iw * ih;
            unsigned p = (3.0f * inter > si[k] + aj) ? (1u << b) : 0u;
            if (k == 0) bits0 |= p;
            else if (k == 1) bits1 |= p;
            else if (k == 2) bits2 |= p;
            else bits3 |= p;
        }
    }
    size_t base = (size_t)rowbase * NWORDS + (size_t)cb * 32 + w;
    g_masks[base + (size_t)(r0 +  0) * NWORDS] = bits0;
    g_masks[base + (size_t)(r0 +  8) * NWORDS] = bits1;
    g_masks[base + (size_t)(r0 + 16) * NWORDS] = bits2;
    g_masks[base + (size_t)(r0 + 24) * NWORDS] = bits3;
}

// ---------------------------------------------------------------------------
// Kernel 4: greedy scan, 128-box chunks, warp 0 = resolution ONLY
// (lanes 1-31 idle -> no divergent serialization), tids 32..255 =
// operand prefetch (c+1) + lag-3 row-OR suppression pipeline.
// ---------------------------------------------------------------------------
__global__ void __launch_bounds__(256)
scan_kernel(const float* __restrict__ scores, float* __restrict__ out) {
    __shared__ unsigned           sup_s[NWORDS];
    __shared__ unsigned long long kbuf[2][2];
    __shared__ int                kcnt[2];
    __shared__ int                s_keep[NPAD];
    __shared__ unsigned long long confb[2][128][2];   // diag 128 cols of chunk
    __shared__ unsigned long long n1b[2][128][2];     // cols of chunk+1
    __shared__ unsigned long long n2b[2][128][2];     // cols of chunk+2

    const int tid = threadIdx.x;
    sup_s[tid] = 0u;
    if (tid == 0) {
        kbuf[0][0] = kbuf[0][1] = kbuf[1][0] = kbuf[1][1] = 0ull;
        kcnt[0] = kcnt[1] = 0;
    }

    // prefill chunk 0 operands: 384 tasks (128 rows x 3 fields), uint4 loads
    if (tid >= 32) {
        for (int t = tid - 32; t < 384; t += 224) {
            int row = t & 127, f = t >> 7;
            const uint4* p = (const uint4*)(g_masks + (size_t)row * NWORDS + 4 * f);
            uint4 v = __ldg(p);
            unsigned long long lo = (unsigned long long)v.x | ((unsigned long long)v.y << 32);
            unsigned long long hi = (unsigned long long)v.z | ((unsigned long long)v.w << 32);
            if (f == 0)      { confb[0][row][0] = lo; confb[0][row][1] = hi; }
            else if (f == 1) { n1b[0][row][0] = lo;   n1b[0][row][1] = hi; }
            else             { n2b[0][row][0] = lo;   n2b[0][row][1] = hi; }
        }
    }
    __syncthreads();

    unsigned long long supfix0 = 0, supfix1 = 0, carry0 = 0, carry1 = 0; // t0
    unsigned b1a = 0u, b1b = 0u, b2a = 0u, b2b = 0u;   // suppression pipeline
    const int w0 = tid - 32;
    const int w1 = (w0 >= 0 && w0 < 32) ? w0 + 224 : -1;
    int nk_local = 0;                                   // t0 only

    for (int c = 0; c < NCH2; c++) {
        // stage A: apply suppression from keeps(c-3) (loaded 2 iters ago)
        if (tid >= 32) {
            if (b2a) sup_s[w0] |= b2a;
            if (w1 >= 0 && b2b) sup_s[w1] |= b2b;
        }
        __syncthreads();   // sup_s(<=c-3), kbuf/kcnt(c-1), operands(c) visible
        if (c > 0 && kcnt[(c - 1) & 1] >= NPAD) break;   // uniform

        if (tid == 0) {
            const int b    = c & 1;
            const int base = c * 128;
            unsigned long long sup0 = *(const unsigned long long*)&sup_s[4 * c];
            unsigned long long sup1 = *(const unsigned long long*)&sup_s[4 * c + 2];
            unsigned long long am0 = ~(sup0 | supfix0);
            unsigned long long am1 = ~(sup1 | supfix1);
            unsigned long long k0 = 0, k1 = 0;
            unsigned long long n1a0 = 0, n1a1 = 0, n2a0 = 0, n2a1 = 0;
            int k2 = nk_local;
            while (am0 | am1) {
                int idx;
                if (am0) idx = __ffsll((long long)am0) - 1;
                else     idx = 64 + __ffsll((long long)am1) - 1;
                if (idx < 64) k0 |= 1ull << idx;
                else          k1 |= 1ull << (idx - 64);
                n1a0 |= n1b[b][idx][0];  n1a1 |= n1b[b][idx][1];
                n2a0 |= n2b[b][idx][0];  n2a1 |= n2b[b][idx][1];
                am0 &= ~confb[b][idx][0];            // diag bit idx included
                am1 &= ~confb[b][idx][1];
                if (idx < 64) am0 &= ~(1ull << idx);
                else          am1 &= ~(1ull << (idx - 64));
                if (k2 < NPAD) s_keep[k2++] = base + idx;
            }
            kbuf[b][0] = k0; kbuf[b][1] = k1;
            kcnt[b] = k2;  nk_local = k2;
            supfix0 = carry0 | n1a0;  supfix1 = carry1 | n1a1;
            carry0  = n2a0;           carry1  = n2a1;
        } else if (tid >= 32) {       // lanes 1-31 of warp 0 stay IDLE
            // prefetch chunk c+1 operands (static addresses)
            const int cn = c + 1;
            if (cn < NCH2) {
                for (int t = tid - 32; t < 384; t += 224) {
                    int row = t & 127, f = t >> 7;
                    int w = 4 * cn + 4 * f;
                    if (w > NWORDS - 4) w = NWORDS - 4;   // tail clamp; unused
                    const uint4* p = (const uint4*)
                        (g_masks + (size_t)(128 * cn + row) * NWORDS + w);
                    uint4 v = __ldg(p);
                    unsigned long long lo = (unsigned long long)v.x | ((unsigned long long)v.y << 32);
                    unsigned long long hi = (unsigned long long)v.z | ((unsigned long long)v.w << 32);
                    int d = cn & 1;
                    if (f == 0)      { confb[d][row][0] = lo; confb[d][row][1] = hi; }
                    else if (f == 1) { n1b[d][row][0] = lo;   n1b[d][row][1] = hi; }
                    else             { n2b[d][row][0] = lo;   n2b[d][row][1] = hi; }
                }
            }
            // stage B: issue row-OR loads for keeps(c-1); applied at c+2
            unsigned a0 = 0u, a1 = 0u;
            if (c > 0) {
                unsigned long long km0 = kbuf[(c - 1) & 1][0];
                unsigned long long km1 = kbuf[(c - 1) & 1][1];
                const size_t pb = (size_t)(c - 1) * 128;
                while (km0) {
                    int l = __ffsll((long long)km0) - 1; km0 &= km0 - 1;
                    const unsigned* row = &g_masks[(pb + l) * NWORDS];
                    a0 |= __ldg(row + w0);
                    if (w1 >= 0) a1 |= __ldg(row + w1);
                }
                while (km1) {
                    int l = __ffsll((long long)km1) - 1; km1 &= km1 - 1;
                    const unsigned* row = &g_masks[(pb + 64 + l) * NWORDS];
                    a0 |= __ldg(row + w0);
                    if (w1 >= 0) a1 |= __ldg(row + w1);
                }
            }
            b2a = b1a; b2b = b1b;
            b1a = a0;  b1b = a1;
        }
    }
    __syncthreads();
    const int nk = (kcnt[0] > kcnt[1]) ? kcnt[0] : kcnt[1];   // cumulative

    // ---- outputs: boxes (300*4) then scores (300*81); zero invalid rows ----
    for (int idx = tid; idx < NPAD * 4; idx += 256) {
        int r = idx >> 2, cc = idx & 3;
        float v = 0.0f;
        if (r < nk) {
            float4 b = g_sbox[s_keep[r]];
            v = (cc == 0) ? b.x : (cc == 1) ? b.y : (cc == 2) ? b.z : b.w;
        }
        out[idx] = v;
    }
    for (int idx = tid; idx < NPAD * CLS; idx += 256) {
        int r = idx / CLS, cc = idx - r * CLS;
        float v = 0.0f;
        if (r < nk)
            v = scores[(size_t)g_orig[s_keep[r]] * CLS + cc];
        out[NPAD * 4 + idx] = v;
    }
}

// ---------------------------------------------------------------------------
extern "C" void kernel_launch(void* const* d_in, const int* in_sizes, int n_in,
                              void* d_out, int out_size) {
    const float* meta      = (const float*)d_in[0];
    const float* deltas    = (const float*)d_in[1];
    const float* proposals = (const float*)d_in[2];
    const float* scores    = (const float*)d_in[3];
    float* out = (float*)d_out;

    decode_kernel<<<NBOX / 8, 256>>>(meta, deltas, proposals, scores);

    cudaFuncSetAttribute(rank_kernel,
                         cudaFuncAttributeMaxDynamicSharedMemorySize, 65536);
    rank_kernel<<<256, 256, 65536>>>();

    mask_kernel<<<1152, 256>>>();

    scan_kernel<<<1, 256>>>(scores, out);
}